// round 2
// baseline (speedup 1.0000x reference)
#include <cuda_runtime.h>
#include <cuda_bf16.h>
#include <cstdint>

// Problem constants
#define BATCH    4096
#define IN_DIM   4096
#define H_DIM    16384
#define TOPK     64

// Eigen gebp k-panel size (k_cache capped at 320, multiple of kr=8).
// Reference (XLA:CPU einsum) accumulates each 320-k panel in a sequential FMA
// chain from zero, then folds the panel into C with a single fp32 add.
#define KC 320

// ---------------------------------------------------------------------------
// Scratch (device globals: allocation inside kernel_launch is forbidden)
// ---------------------------------------------------------------------------
__device__ float g_features[(size_t)BATCH * H_DIM];   // 256 MB encoder output
__device__ float g_WdT[(size_t)H_DIM * IN_DIM];       // 256 MB W_dec transposed [H, I]
__device__ float g_top_vals[(size_t)BATCH * TOPK];
__device__ int   g_top_idx [(size_t)BATCH * TOPK];

// ---------------------------------------------------------------------------
// Encoder: features = relu(x @ W_enc^T + b_enc), fp32.
// Accumulation EXACTLY mimics Eigen gebp panelling:
//   total = 0
//   for each k-panel of KC=320 (last panel 256):
//       chunk = sequential fma chain over the panel, ascending k, from 0
//       total = total + chunk            (single fp32 add)
// Tile: 128x128, BK=16, 256 threads, 8x8 per-thread microtile.
// ---------------------------------------------------------------------------
#define BM 128
#define BN 128
#define BK 16

__global__ __launch_bounds__(256, 1)
void encoder_kernel(const float* __restrict__ A,   // x      [BATCH, IN_DIM]
                    const float* __restrict__ B,   // W_enc  [H_DIM, IN_DIM]
                    const float* __restrict__ bias)
{
    __shared__ float As[BK][BM];
    __shared__ float Bs[BK][BN];

    const int bn  = blockIdx.x;          // H tile
    const int bm  = blockIdx.y;          // batch tile
    const int tid = threadIdx.x;
    const int tx  = tid & 15;            // 0..15  -> n
    const int ty  = tid >> 4;            // 0..15  -> m

    const float* Ablk = A + (size_t)bm * BM * IN_DIM;
    const float* Bblk = B + (size_t)bn * BN * IN_DIM;

    float acc[8][8];     // current k-panel (chunk) accumulator
    float tot[8][8];     // panel-folded total
#pragma unroll
    for (int i = 0; i < 8; ++i)
#pragma unroll
        for (int j = 0; j < 8; ++j) { acc[i][j] = 0.0f; tot[i][j] = 0.0f; }

    for (int kt = 0; kt < IN_DIM; kt += BK) {
        // Load tiles: 128 rows x 16 k = 512 float4 per operand; 2 per thread.
#pragma unroll
        for (int j = 0; j < 2; ++j) {
            const int idx = tid * 2 + j;
            const int row = idx >> 2;
            const int kq  = (idx & 3) * 4;
            float4 av = *(const float4*)(Ablk + (size_t)row * IN_DIM + kt + kq);
            As[kq + 0][row] = av.x; As[kq + 1][row] = av.y;
            As[kq + 2][row] = av.z; As[kq + 3][row] = av.w;
            float4 bv = *(const float4*)(Bblk + (size_t)row * IN_DIM + kt + kq);
            Bs[kq + 0][row] = bv.x; Bs[kq + 1][row] = bv.y;
            Bs[kq + 2][row] = bv.z; Bs[kq + 3][row] = bv.w;
        }
        __syncthreads();

#pragma unroll
        for (int kk = 0; kk < BK; ++kk) {
            float a[8], b[8];
            *(float4*)(a)     = *(const float4*)&As[kk][ty * 8];
            *(float4*)(a + 4) = *(const float4*)&As[kk][ty * 8 + 4];
            *(float4*)(b)     = *(const float4*)&Bs[kk][tx * 8];
            *(float4*)(b + 4) = *(const float4*)&Bs[kk][tx * 8 + 4];
#pragma unroll
            for (int i = 0; i < 8; ++i)
#pragma unroll
                for (int j = 0; j < 8; ++j)
                    acc[i][j] = fmaf(a[i], b[j], acc[i][j]);
        }
        __syncthreads();

        // Fold the panel at every KC boundary and at the end of K.
        const int knext = kt + BK;
        if ((knext % KC) == 0 || knext == IN_DIM) {
#pragma unroll
            for (int i = 0; i < 8; ++i)
#pragma unroll
                for (int j = 0; j < 8; ++j) {
                    tot[i][j] = tot[i][j] + acc[i][j];
                    acc[i][j] = 0.0f;
                }
        }
    }

    // Epilogue: + bias, relu, store
#pragma unroll
    for (int i = 0; i < 8; ++i) {
        const int m = bm * BM + ty * 8 + i;
        float* crow = g_features + (size_t)m * H_DIM + bn * BN;
#pragma unroll
        for (int j = 0; j < 8; ++j) {
            const int n = bn * BN + tx * 8 + j;
            float v = tot[i][j] + bias[n];
            crow[tx * 8 + j] = v > 0.0f ? v : 0.0f;
        }
    }
}

// ---------------------------------------------------------------------------
// W_dec [IN_DIM, H_DIM] -> g_WdT [H_DIM, IN_DIM]
// ---------------------------------------------------------------------------
__global__ void transpose_kernel(const float* __restrict__ in)
{
    __shared__ float tile[32][33];
    const int c0 = blockIdx.x * 32;  // H coordinate
    const int r0 = blockIdx.y * 32;  // I coordinate
    const int x = threadIdx.x, y = threadIdx.y;
#pragma unroll
    for (int j = 0; j < 32; j += 8)
        tile[y + j][x] = in[(size_t)(r0 + y + j) * H_DIM + c0 + x];
    __syncthreads();
#pragma unroll
    for (int j = 0; j < 32; j += 8)
        g_WdT[(size_t)(c0 + y + j) * IN_DIM + r0 + x] = tile[x][y + j];
}

// ---------------------------------------------------------------------------
// Per-row exact top-K: 4-pass radix select on float bits (all values >= 0
// after relu, so key = bits | 0x80000000 is monotonic). Ties at the threshold
// value are broken by lowest index (matches jax.lax.top_k).
// One block of 256 threads per row.
// ---------------------------------------------------------------------------
__global__ void topk_kernel(float* __restrict__ sparse_out)
{
    const int row = blockIdx.x;
    const int tid = threadIdx.x;
    const float* frow = g_features + (size_t)row * H_DIM;

    __shared__ unsigned int hist[256];
    __shared__ int s_bin, s_rem;

    unsigned int prefix = 0;
    int remaining = TOPK;

    for (int byte = 3; byte >= 0; --byte) {
        hist[tid] = 0;
        __syncthreads();
        const int shift = byte * 8;
        const unsigned int prefmask = (byte == 3) ? 0u : (0xFFFFFFFFu << (shift + 8));
        for (int j = tid; j < H_DIM; j += 256) {
            unsigned int u = __float_as_uint(frow[j]) | 0x80000000u;
            if ((u & prefmask) == prefix)
                atomicAdd(&hist[(u >> shift) & 0xFF], 1u);
        }
        __syncthreads();
        if (tid == 0) {
            int rem = remaining;
            int bsel = 0;
            for (int b2 = 255; b2 >= 0; --b2) {
                int c = (int)hist[b2];
                if (rem <= c) { bsel = b2; break; }
                rem -= c;
            }
            s_bin = bsel; s_rem = rem;
        }
        __syncthreads();
        prefix |= ((unsigned int)s_bin) << shift;
        remaining = s_rem;
        __syncthreads();
    }

    const unsigned int T = prefix;   // exact key of the K-th largest element

    __shared__ int cnt, tie_cnt;
    __shared__ int tie_idx[256];
    if (tid == 0) { cnt = 0; tie_cnt = 0; }
    __syncthreads();

    for (int j = tid; j < H_DIM; j += 256) {
        const float v = frow[j];
        const unsigned int u = __float_as_uint(v) | 0x80000000u;
        if (u > T) {
            const int s = atomicAdd(&cnt, 1);
            g_top_vals[(size_t)row * TOPK + s] = v;
            g_top_idx [(size_t)row * TOPK + s] = j;
            sparse_out[(size_t)row * H_DIM + j] = v;
        } else if (u == T) {
            const int s = atomicAdd(&tie_cnt, 1);
            if (s < 256) tie_idx[s] = j;
        }
    }
    __syncthreads();

    if (tid == 0) {
        const int need = TOPK - cnt;   // how many threshold-equal elements to take
        if (tie_cnt <= 256) {
            // lowest indices first
            for (int a = 1; a < tie_cnt; ++a) {
                int v2 = tie_idx[a]; int b2 = a - 1;
                while (b2 >= 0 && tie_idx[b2] > v2) { tie_idx[b2 + 1] = tie_idx[b2]; --b2; }
                tie_idx[b2 + 1] = v2;
            }
            for (int q = 0; q < need; ++q) {
                const int j = tie_idx[q];
                const float v = frow[j];
                g_top_vals[(size_t)row * TOPK + cnt + q] = v;
                g_top_idx [(size_t)row * TOPK + cnt + q] = j;
                sparse_out[(size_t)row * H_DIM + j] = v;
            }
        } else {
            // degenerate fallback (massive ties): serial in-order scan
            int got = 0;
            for (int j = 0; j < H_DIM && got < need; ++j) {
                const unsigned int u = __float_as_uint(frow[j]) | 0x80000000u;
                if (u == T) {
                    const float v = frow[j];
                    g_top_vals[(size_t)row * TOPK + cnt + got] = v;
                    g_top_idx [(size_t)row * TOPK + cnt + got] = j;
                    sparse_out[(size_t)row * H_DIM + j] = v;
                    ++got;
                }
            }
        }
    }
}

// ---------------------------------------------------------------------------
// Sparse decode: recon[b,:] = sum_{k<64} val_k * WdT[idx_k, :]
// One block per batch row, 256 threads, 16 fp32 accumulators per thread.
// ---------------------------------------------------------------------------
__global__ void decode_kernel(float* __restrict__ recon)
{
    const int b = blockIdx.x;
    const int t = threadIdx.x;

    float acc[16];
#pragma unroll
    for (int i = 0; i < 16; ++i) acc[i] = 0.0f;

    for (int k = 0; k < TOPK; ++k) {
        const float val = g_top_vals[(size_t)b * TOPK + k];
        const int   idx = g_top_idx [(size_t)b * TOPK + k];
        const float4* wr = (const float4*)(g_WdT + (size_t)idx * IN_DIM);
#pragma unroll
        for (int q = 0; q < 4; ++q) {
            const float4 w = __ldg(&wr[t + q * 256]);
            acc[q * 4 + 0] = fmaf(val, w.x, acc[q * 4 + 0]);
            acc[q * 4 + 1] = fmaf(val, w.y, acc[q * 4 + 1]);
            acc[q * 4 + 2] = fmaf(val, w.z, acc[q * 4 + 2]);
            acc[q * 4 + 3] = fmaf(val, w.w, acc[q * 4 + 3]);
        }
    }

    float4* out = (float4*)(recon + (size_t)b * IN_DIM);
#pragma unroll
    for (int q = 0; q < 4; ++q)
        out[t + q * 256] = make_float4(acc[q * 4 + 0], acc[q * 4 + 1],
                                       acc[q * 4 + 2], acc[q * 4 + 3]);
}

// ---------------------------------------------------------------------------
// Launch
// ---------------------------------------------------------------------------
extern "C" void kernel_launch(void* const* d_in, const int* in_sizes, int n_in,
                              void* d_out, int out_size)
{
    const float* x     = (const float*)d_in[0];
    const float* W_enc = (const float*)d_in[1];
    const float* b_enc = (const float*)d_in[2];
    const float* W_dec = (const float*)d_in[3];

    float* out    = (float*)d_out;
    float* sparse = out;                                   // [BATCH, H_DIM]
    float* recon  = out + (size_t)BATCH * H_DIM;           // [BATCH, IN_DIM]

    // zero the sparse output region (scatter writes only K per row)
    cudaMemsetAsync(sparse, 0, (size_t)BATCH * H_DIM * sizeof(float));

    // encoder GEMM + bias + relu
    dim3 eg(H_DIM / BN, BATCH / BM);
    encoder_kernel<<<eg, 256>>>(x, W_enc, b_enc);

    // transpose W_dec for coalesced sparse decode (independent of encoder)
    dim3 tg(H_DIM / 32, IN_DIM / 32);
    transpose_kernel<<<tg, dim3(32, 8)>>>(W_dec);

    // exact per-row top-K + scatter into sparse output
    topk_kernel<<<BATCH, 256>>>(sparse);

    // sparse decode
    decode_kernel<<<BATCH, 256>>>(recon);
}

// round 5
// speedup vs baseline: 2.3070x; 2.3070x over previous
#include <cuda_runtime.h>
#include <cuda_bf16.h>
#include <cstdint>

#define BATCH    4096
#define IN_DIM   4096
#define H_DIM    16384
#define TOPK     64
#define KC       320            // Eigen gebp k-panel (exact-recompute chain)
#define DELTA    1.2e-2f        // >= 4*max approx error

// split GEMM dims
#define KP   (3 * IN_DIM)       // 12288
#define GBM  128
#define GBN  128
#define GBK  32
#define NKT  (KP / GBK)         // 384
#define ROWB 80                 // smem row stride bytes (64 data + 16 pad)
#define STG  ((GBM + GBN) * ROWB)   // 20480 bytes per stage

// ---------------------------------------------------------------------------
// Device scratch (NEVER pass these symbols as kernel args from host: the host
// sees the shadow symbol and ATS makes the bogus dereference "work"-but-wrong)
// ---------------------------------------------------------------------------
__device__ float          g_features[(size_t)BATCH * H_DIM];     // 256 MB
__device__ float          g_WdT[(size_t)H_DIM * IN_DIM];         // 256 MB
__device__ __nv_bfloat16  g_Asp[(size_t)BATCH * KP];             // 96 MB  [Ah|Ah|Al]
__device__ __nv_bfloat16  g_Bsp[(size_t)H_DIM * KP];             // 384 MB [Bh|Bl|Bh]
__device__ float          g_top_vals[(size_t)BATCH * TOPK];
__device__ int            g_top_idx [(size_t)BATCH * TOPK];
__device__ float          g_vT[BATCH];
__device__ int            g_win_idx[(size_t)BATCH * 64];
__device__ int            g_win_cnt[BATCH];

__device__ __forceinline__ uint32_t smem_to_u32(const void* p) {
    uint32_t a;
    asm("{ .reg .u64 t; cvta.to.shared.u64 t, %1; cvt.u32.u64 %0, t; }"
        : "=r"(a) : "l"(p));
    return a;
}

// ---------------------------------------------------------------------------
// Split kernels: fp32 -> (hi, lo) bf16 pair layouts for the 3-term product
//   x*w ~= xh*wh + xh*wl + xl*wh   (A' = [Ah|Ah|Al], B' = [Bh|Bl|Bh])
// ---------------------------------------------------------------------------
__global__ void split_x_kernel(const float* __restrict__ x)
{
    const size_t gid = (size_t)blockIdx.x * blockDim.x + threadIdx.x;
    const size_t m   = gid / (IN_DIM / 4);
    const int    kq  = (int)(gid % (IN_DIM / 4)) * 4;
    float4 v = *(const float4*)(x + m * IN_DIM + kq);
    __nv_bfloat16 h[4], l[4];
    float f[4] = {v.x, v.y, v.z, v.w};
#pragma unroll
    for (int i = 0; i < 4; ++i) {
        h[i] = __float2bfloat16_rn(f[i]);
        l[i] = __float2bfloat16_rn(f[i] - __bfloat162float(h[i]));
    }
    __nv_bfloat16* row = g_Asp + m * KP;
    *(uint2*)(row + kq)              = *(uint2*)h;
    *(uint2*)(row + IN_DIM + kq)     = *(uint2*)h;
    *(uint2*)(row + 2 * IN_DIM + kq) = *(uint2*)l;
}

__global__ void split_w_kernel(const float* __restrict__ w)
{
    const size_t gid = (size_t)blockIdx.x * blockDim.x + threadIdx.x;
    const size_t m   = gid / (IN_DIM / 4);
    const int    kq  = (int)(gid % (IN_DIM / 4)) * 4;
    float4 v = *(const float4*)(w + m * IN_DIM + kq);
    __nv_bfloat16 h[4], l[4];
    float f[4] = {v.x, v.y, v.z, v.w};
#pragma unroll
    for (int i = 0; i < 4; ++i) {
        h[i] = __float2bfloat16_rn(f[i]);
        l[i] = __float2bfloat16_rn(f[i] - __bfloat162float(h[i]));
    }
    __nv_bfloat16* row = g_Bsp + m * KP;
    *(uint2*)(row + kq)              = *(uint2*)h;
    *(uint2*)(row + IN_DIM + kq)     = *(uint2*)l;
    *(uint2*)(row + 2 * IN_DIM + kq) = *(uint2*)h;
}

// ---------------------------------------------------------------------------
// bf16 GEMM via mma.sync.m16n8k16. CTA 128x128, 8 warps (2m x 4n), warp tile
// 64x32. 2-stage cp.async pipeline, ldmatrix fragment loads.
// A/B read from the device globals directly (see note above).
// ---------------------------------------------------------------------------
__device__ __forceinline__ void ldm_x4(uint32_t* r, uint32_t addr)
{
    asm volatile("ldmatrix.sync.aligned.m8n8.x4.shared.b16 {%0,%1,%2,%3}, [%4];"
                 : "=r"(r[0]), "=r"(r[1]), "=r"(r[2]), "=r"(r[3]) : "r"(addr));
}
__device__ __forceinline__ void mma16816(float* c, const uint32_t* a,
                                         uint32_t b0, uint32_t b1)
{
    asm volatile("mma.sync.aligned.m16n8k16.row.col.f32.bf16.bf16.f32 "
                 "{%0,%1,%2,%3}, {%4,%5,%6,%7}, {%8,%9}, {%0,%1,%2,%3};"
                 : "+f"(c[0]), "+f"(c[1]), "+f"(c[2]), "+f"(c[3])
                 : "r"(a[0]), "r"(a[1]), "r"(a[2]), "r"(a[3]), "r"(b0), "r"(b1));
}
__device__ __forceinline__ void cp16(uint32_t dst, const void* src)
{
    asm volatile("cp.async.cg.shared.global [%0], [%1], 16;"
                 :: "r"(dst), "l"(src));
}

__global__ void __launch_bounds__(256, 2)
gemm_kernel(const float* __restrict__ bias)
{
    __shared__ char sm[2 * STG];
    const uint32_t sbase = smem_to_u32(sm);
    const int tid  = threadIdx.x;
    const int wid  = tid >> 5, lane = tid & 31;
    const int wm   = wid & 1;          // 0..1 -> m offset 64*wm
    const int wn   = wid >> 1;         // 0..3 -> n offset 32*wn
    const int bn   = blockIdx.x, bm = blockIdx.y;

    const __nv_bfloat16* Ab = g_Asp + (size_t)bm * GBM * KP;
    const __nv_bfloat16* Bb = g_Bsp + (size_t)bn * GBN * KP;

    float acc[4][4][4];
#pragma unroll
    for (int i = 0; i < 4; ++i)
#pragma unroll
        for (int j = 0; j < 4; ++j)
#pragma unroll
            for (int q = 0; q < 4; ++q) acc[i][j][q] = 0.0f;

    // per-thread copy chunks: 1024 16B chunks per stage (A:512, B:512)
    auto copy_stage = [&](int buf, int t) {
        const size_t kel = (size_t)t * GBK;
        const uint32_t sb = sbase + buf * STG;
#pragma unroll
        for (int i = 0; i < 4; ++i) {
            const int c = tid + 256 * i;         // 0..1023
            const int r = (c >> 2) & 127;        // row within operand
            const int q = c & 3;                 // 16B chunk within 64B row
            if (c < 512)
                cp16(sb + r * ROWB + q * 16,
                     (const char*)(Ab + (size_t)r * KP + kel) + q * 16);
            else
                cp16(sb + GBM * ROWB + r * ROWB + q * 16,
                     (const char*)(Bb + (size_t)r * KP + kel) + q * 16);
        }
    };

    copy_stage(0, 0);
    asm volatile("cp.async.commit_group;");

    const int lrow = (lane & 7) + ((lane >> 3) & 1) * 8;   // 0..15
    const int lcol = (lane >> 4) << 4;                     // 0 or 16 bytes

    for (int t = 0; t < NKT; ++t) {
        const int buf = t & 1;
        if (t + 1 < NKT) copy_stage(buf ^ 1, t + 1);
        asm volatile("cp.async.commit_group;");
        asm volatile("cp.async.wait_group %0;" :: "n"(1));
        __syncthreads();

        const uint32_t aBase = sbase + buf * STG + (wm * 64) * ROWB;
        const uint32_t bBase = sbase + buf * STG + GBM * ROWB + (wn * 32) * ROWB;
#pragma unroll
        for (int ks = 0; ks < 2; ++ks) {
            uint32_t af[4][4], bf[2][4];
#pragma unroll
            for (int mi = 0; mi < 4; ++mi)
                ldm_x4(af[mi], aBase + (mi * 16 + lrow) * ROWB + ks * 32 + lcol);
#pragma unroll
            for (int bj = 0; bj < 2; ++bj)
                ldm_x4(bf[bj], bBase + (bj * 16 + lrow) * ROWB + ks * 32 + lcol);
#pragma unroll
            for (int mi = 0; mi < 4; ++mi)
#pragma unroll
                for (int ni = 0; ni < 4; ++ni)
                    mma16816(acc[mi][ni], af[mi],
                             bf[ni >> 1][ni & 1], bf[ni >> 1][(ni & 1) + 2]);
        }
        __syncthreads();
    }

    // epilogue: bias + relu + store
#pragma unroll
    for (int mi = 0; mi < 4; ++mi) {
#pragma unroll
        for (int ni = 0; ni < 4; ++ni) {
            const int m = bm * GBM + wm * 64 + mi * 16 + (lane >> 2);
            const int n = bn * GBN + wn * 32 + ni * 8 + (lane & 3) * 2;
            const float b0 = __ldg(bias + n), b1 = __ldg(bias + n + 1);
            float* p0 = g_features + (size_t)m * H_DIM + n;
            float* p1 = g_features + (size_t)(m + 8) * H_DIM + n;
            float2 v0, v1;
            v0.x = fmaxf(acc[mi][ni][0] + b0, 0.0f);
            v0.y = fmaxf(acc[mi][ni][1] + b1, 0.0f);
            v1.x = fmaxf(acc[mi][ni][2] + b0, 0.0f);
            v1.y = fmaxf(acc[mi][ni][3] + b1, 0.0f);
            *(float2*)p0 = v0;
            *(float2*)p1 = v1;
        }
    }
}

// ---------------------------------------------------------------------------
// W_dec [IN_DIM, H_DIM] -> g_WdT [H_DIM, IN_DIM]
// ---------------------------------------------------------------------------
__global__ void transpose_kernel(const float* __restrict__ in)
{
    __shared__ float tile[32][33];
    const int c0 = blockIdx.x * 32, r0 = blockIdx.y * 32;
    const int x = threadIdx.x, y = threadIdx.y;
#pragma unroll
    for (int j = 0; j < 32; j += 8)
        tile[y + j][x] = in[(size_t)(r0 + y + j) * H_DIM + c0 + x];
    __syncthreads();
#pragma unroll
    for (int j = 0; j < 32; j += 8)
        g_WdT[(size_t)(c0 + y + j) * IN_DIM + r0 + x] = tile[x][y + j];
}

// ---------------------------------------------------------------------------
// Top-K on approx features (radix select) + ambiguity-window collection
// ---------------------------------------------------------------------------
__global__ void topk_kernel()
{
    const int row = blockIdx.x;
    const int tid = threadIdx.x;
    const float* frow = g_features + (size_t)row * H_DIM;

    __shared__ unsigned int hist[256];
    __shared__ int s_bin, s_rem;
    if (tid == 0) g_win_cnt[row] = 0;

    unsigned int prefix = 0;
    int remaining = TOPK;
    for (int byte = 3; byte >= 0; --byte) {
        hist[tid] = 0;
        __syncthreads();
        const int shift = byte * 8;
        const unsigned int pm = (byte == 3) ? 0u : (0xFFFFFFFFu << (shift + 8));
        for (int j = tid; j < H_DIM; j += 256) {
            unsigned int u = __float_as_uint(frow[j]) | 0x80000000u;
            if ((u & pm) == prefix) atomicAdd(&hist[(u >> shift) & 0xFF], 1u);
        }
        __syncthreads();
        if (tid == 0) {
            int rem = remaining, bsel = 0;
            for (int b2 = 255; b2 >= 0; --b2) {
                int c = (int)hist[b2];
                if (rem <= c) { bsel = b2; break; }
                rem -= c;
            }
            s_bin = bsel; s_rem = rem;
        }
        __syncthreads();
        prefix |= ((unsigned int)s_bin) << shift;
        remaining = s_rem;
        __syncthreads();
    }
    const unsigned int T = prefix;
    const float vT = __uint_as_float(T ^ 0x80000000u);
    if (tid == 0) g_vT[row] = vT;

    __shared__ int cnt, tie_cnt;
    __shared__ int tie_idx[256];
    if (tid == 0) { cnt = 0; tie_cnt = 0; }
    __syncthreads();

    for (int j = tid; j < H_DIM; j += 256) {
        const float v = frow[j];
        const unsigned int u = __float_as_uint(v) | 0x80000000u;
        if (fabsf(v - vT) <= DELTA) {
            const int w = atomicAdd(&g_win_cnt[row], 1);
            if (w < 64) g_win_idx[(size_t)row * 64 + w] = j;
        }
        if (u > T) {
            const int s = atomicAdd(&cnt, 1);
            g_top_vals[(size_t)row * TOPK + s] = v;
            g_top_idx [(size_t)row * TOPK + s] = j;
        } else if (u == T) {
            const int s = atomicAdd(&tie_cnt, 1);
            if (s < 256) tie_idx[s] = j;
        }
    }
    __syncthreads();

    if (tid == 0) {
        const int need = TOPK - cnt;
        for (int a = 1; a < tie_cnt && a < 256; ++a) {
            int v2 = tie_idx[a]; int b2 = a - 1;
            while (b2 >= 0 && tie_idx[b2] > v2) { tie_idx[b2 + 1] = tie_idx[b2]; --b2; }
            tie_idx[b2 + 1] = v2;
        }
        for (int q = 0; q < need; ++q) {
            const int j = tie_idx[q];
            g_top_vals[(size_t)row * TOPK + cnt + q] = frow[j];
            g_top_idx [(size_t)row * TOPK + cnt + q] = j;
        }
    }
}

// ---------------------------------------------------------------------------
// Boundary fixup: recompute exact Eigen-chunked fp32 dots for all window
// candidates, re-award the boundary slots by exact value (ties: lowest idx).
// ---------------------------------------------------------------------------
__global__ void fixup_kernel(const float* __restrict__ x,
                             const float* __restrict__ W,
                             const float* __restrict__ bias)
{
    const int row = blockIdx.x;
    const int cnt = min(g_win_cnt[row], 64);
    if (cnt < 2) return;
    const int t = threadIdx.x;

    __shared__ float ex_val[64];
    __shared__ int   ex_idx[64];

    if (t < cnt) {
        const int h = g_win_idx[(size_t)row * 64 + t];
        const float* xr = x + (size_t)row * IN_DIM;
        const float* wr = W + (size_t)h * IN_DIM;
        float tot = 0.0f;
        int k = 0;
#pragma unroll 1
        for (int p = 0; p < 13; ++p) {
            const int len = (p < 12) ? KC : (IN_DIM - 12 * KC);
            float acc = 0.0f;
            for (int q = 0; q < len; q += 4) {
                const float4 xv = *(const float4*)(xr + k + q);
                const float4 wv = *(const float4*)(wr + k + q);
                acc = fmaf(xv.x, wv.x, acc);
                acc = fmaf(xv.y, wv.y, acc);
                acc = fmaf(xv.z, wv.z, acc);
                acc = fmaf(xv.w, wv.w, acc);
            }
            tot += acc;
            k += len;
        }
        float v = tot + bias[h];
        ex_val[t] = v > 0.0f ? v : 0.0f;
        ex_idx[t] = h;
    }
    __syncthreads();

    if (t == 0) {
        const float vT = g_vT[row];
        float* vals = g_top_vals + (size_t)row * TOPK;
        int*   idxs = g_top_idx  + (size_t)row * TOPK;
        int slots[TOPK], nslots = 0;
        for (int s = 0; s < TOPK; ++s)
            if (vals[s] <= vT + DELTA) slots[nslots++] = s;
        bool used[64];
        for (int c = 0; c < cnt; ++c) used[c] = false;
        for (int q = 0; q < nslots; ++q) {
            int best = -1;
            for (int c = 0; c < cnt; ++c) {
                if (used[c]) continue;
                if (best < 0 ||
                    ex_val[c] > ex_val[best] ||
                    (ex_val[c] == ex_val[best] && ex_idx[c] < ex_idx[best]))
                    best = c;
            }
            used[best] = true;
            vals[slots[q]] = ex_val[best];
            idxs[slots[q]] = ex_idx[best];
        }
    }
}

// ---------------------------------------------------------------------------
// Sort each row's 64 picks by index (determinism) and scatter to sparse out.
// ---------------------------------------------------------------------------
__global__ void scatter_kernel(float* __restrict__ sparse)
{
    const int row = blockIdx.x;
    const int t = threadIdx.x;   // 64
    __shared__ float sv[TOPK];
    __shared__ int   si[TOPK];
    sv[t] = g_top_vals[(size_t)row * TOPK + t];
    si[t] = g_top_idx [(size_t)row * TOPK + t];
    __syncthreads();
    for (int p = 0; p < TOPK; ++p) {
        const int base = p & 1;
        if (t < TOPK / 2) {
            const int i = base + 2 * t;
            if (i + 1 < TOPK && si[i] > si[i + 1]) {
                int ti = si[i]; si[i] = si[i + 1]; si[i + 1] = ti;
                float tv = sv[i]; sv[i] = sv[i + 1]; sv[i + 1] = tv;
            }
        }
        __syncthreads();
    }
    g_top_vals[(size_t)row * TOPK + t] = sv[t];
    g_top_idx [(size_t)row * TOPK + t] = si[t];
    sparse[(size_t)row * H_DIM + si[t]] = sv[t];
}

// ---------------------------------------------------------------------------
// Sparse decode: recon[b,:] = sum_k val_k * WdT[idx_k, :]
// ---------------------------------------------------------------------------
__global__ void decode_kernel(float* __restrict__ recon)
{
    const int b = blockIdx.x;
    const int t = threadIdx.x;
    float acc[16];
#pragma unroll
    for (int i = 0; i < 16; ++i) acc[i] = 0.0f;
    for (int k = 0; k < TOPK; ++k) {
        const float val = g_top_vals[(size_t)b * TOPK + k];
        const int   idx = g_top_idx [(size_t)b * TOPK + k];
        const float4* wr = (const float4*)(g_WdT + (size_t)idx * IN_DIM);
#pragma unroll
        for (int q = 0; q < 4; ++q) {
            const float4 w = __ldg(&wr[t + q * 256]);
            acc[q * 4 + 0] = fmaf(val, w.x, acc[q * 4 + 0]);
            acc[q * 4 + 1] = fmaf(val, w.y, acc[q * 4 + 1]);
            acc[q * 4 + 2] = fmaf(val, w.z, acc[q * 4 + 2]);
            acc[q * 4 + 3] = fmaf(val, w.w, acc[q * 4 + 3]);
        }
    }
    float4* out = (float4*)(recon + (size_t)b * IN_DIM);
#pragma unroll
    for (int q = 0; q < 4; ++q)
        out[t + q * 256] = make_float4(acc[q * 4 + 0], acc[q * 4 + 1],
                                       acc[q * 4 + 2], acc[q * 4 + 3]);
}

// ---------------------------------------------------------------------------
// Launch
// ---------------------------------------------------------------------------
extern "C" void kernel_launch(void* const* d_in, const int* in_sizes, int n_in,
                              void* d_out, int out_size)
{
    const float* x     = (const float*)d_in[0];
    const float* W_enc = (const float*)d_in[1];
    const float* b_enc = (const float*)d_in[2];
    const float* W_dec = (const float*)d_in[3];

    float* out    = (float*)d_out;
    float* sparse = out;
    float* recon  = out + (size_t)BATCH * H_DIM;

    cudaMemsetAsync(sparse, 0, (size_t)BATCH * H_DIM * sizeof(float));

    split_x_kernel<<<(BATCH * IN_DIM / 4) / 256, 256>>>(x);
    split_w_kernel<<<(H_DIM * IN_DIM / 4) / 256, 256>>>(W_enc);

    dim3 gg(H_DIM / GBN, BATCH / GBM);
    gemm_kernel<<<gg, 256>>>(b_enc);

    dim3 tg(H_DIM / 32, IN_DIM / 32);
    transpose_kernel<<<tg, dim3(32, 8)>>>(W_dec);

    topk_kernel<<<BATCH, 256>>>();
    fixup_kernel<<<BATCH, 64>>>(x, W_enc, b_enc);
    scatter_kernel<<<BATCH, TOPK>>>(sparse);
    decode_kernel<<<BATCH, 256>>>(recon);
}

// round 6
// speedup vs baseline: 3.7234x; 1.6140x over previous
#include <cuda_runtime.h>
#include <cuda_bf16.h>
#include <cstdint>

#define BATCH    4096
#define IN_DIM   4096
#define H_DIM    16384
#define TOPK     64
#define KC       320            // Eigen gebp k-panel (exact-recompute chain)
#define DELTA    0.035f         // >= 2*max screening error (~9e-3); 2x margin
#define MAXCAND  256

// screening GEMM dims (hi-only bf16, K = IN_DIM)
#define KP   IN_DIM             // 4096
#define GBM  128
#define GBN  128
#define GBK  32
#define NKT  (KP / GBK)         // 128
#define ROWB 80                 // smem row stride bytes (64 data + 16 pad)
#define STG  ((GBM + GBN) * ROWB)

// ---------------------------------------------------------------------------
// Device scratch (never pass these symbols as host-side kernel args!)
// ---------------------------------------------------------------------------
__device__ float          g_features[(size_t)BATCH * H_DIM];     // 256 MB approx
__device__ float          g_WdT[(size_t)H_DIM * IN_DIM];         // 256 MB
__device__ __nv_bfloat16  g_Asp[(size_t)BATCH * KP];             // 32 MB  xh
__device__ __nv_bfloat16  g_Bsp[(size_t)H_DIM * KP];             // 128 MB wh
__device__ float          g_top_vals[(size_t)BATCH * TOPK];
__device__ int            g_top_idx [(size_t)BATCH * TOPK];
__device__ int            g_cand_idx[(size_t)BATCH * MAXCAND];
__device__ int            g_cand_cnt[BATCH];

__device__ __forceinline__ uint32_t smem_to_u32(const void* p) {
    uint32_t a;
    asm("{ .reg .u64 t; cvta.to.shared.u64 t, %1; cvt.u32.u64 %0, t; }"
        : "=r"(a) : "l"(p));
    return a;
}

// ---------------------------------------------------------------------------
// Split kernels: keep only the bf16 hi part (screening needs ~1.6e-3 accuracy)
// ---------------------------------------------------------------------------
__global__ void split_x_kernel(const float* __restrict__ x)
{
    const size_t gid = (size_t)blockIdx.x * blockDim.x + threadIdx.x;
    const size_t m   = gid / (IN_DIM / 4);
    const int    kq  = (int)(gid % (IN_DIM / 4)) * 4;
    float4 v = *(const float4*)(x + m * IN_DIM + kq);
    __nv_bfloat16 h[4] = { __float2bfloat16_rn(v.x), __float2bfloat16_rn(v.y),
                           __float2bfloat16_rn(v.z), __float2bfloat16_rn(v.w) };
    *(uint2*)(g_Asp + m * KP + kq) = *(uint2*)h;
}

__global__ void split_w_kernel(const float* __restrict__ w)
{
    const size_t gid = (size_t)blockIdx.x * blockDim.x + threadIdx.x;
    const size_t m   = gid / (IN_DIM / 4);
    const int    kq  = (int)(gid % (IN_DIM / 4)) * 4;
    float4 v = *(const float4*)(w + m * IN_DIM + kq);
    __nv_bfloat16 h[4] = { __float2bfloat16_rn(v.x), __float2bfloat16_rn(v.y),
                           __float2bfloat16_rn(v.z), __float2bfloat16_rn(v.w) };
    *(uint2*)(g_Bsp + m * KP + kq) = *(uint2*)h;
}

// ---------------------------------------------------------------------------
// Screening GEMM: approx features = relu(xh @ wh^T + bias).
// mma.sync m16n8k16 bf16; CTA 128x128, 8 warps, warp tile 64x32; 2-stage
// cp.async pipeline. (HMMA-issue-bound at rt~16 on sm_103; K is the lever.)
// ---------------------------------------------------------------------------
__device__ __forceinline__ void ldm_x4(uint32_t* r, uint32_t addr)
{
    asm volatile("ldmatrix.sync.aligned.m8n8.x4.shared.b16 {%0,%1,%2,%3}, [%4];"
                 : "=r"(r[0]), "=r"(r[1]), "=r"(r[2]), "=r"(r[3]) : "r"(addr));
}
__device__ __forceinline__ void mma16816(float* c, const uint32_t* a,
                                         uint32_t b0, uint32_t b1)
{
    asm volatile("mma.sync.aligned.m16n8k16.row.col.f32.bf16.bf16.f32 "
                 "{%0,%1,%2,%3}, {%4,%5,%6,%7}, {%8,%9}, {%0,%1,%2,%3};"
                 : "+f"(c[0]), "+f"(c[1]), "+f"(c[2]), "+f"(c[3])
                 : "r"(a[0]), "r"(a[1]), "r"(a[2]), "r"(a[3]), "r"(b0), "r"(b1));
}
__device__ __forceinline__ void cp16(uint32_t dst, const void* src)
{
    asm volatile("cp.async.cg.shared.global [%0], [%1], 16;"
                 :: "r"(dst), "l"(src));
}

__global__ void __launch_bounds__(256, 2)
gemm_kernel(const float* __restrict__ bias)
{
    __shared__ char sm[2 * STG];
    const uint32_t sbase = smem_to_u32(sm);
    const int tid  = threadIdx.x;
    const int wid  = tid >> 5, lane = tid & 31;
    const int wm   = wid & 1;
    const int wn   = wid >> 1;
    const int bn   = blockIdx.x, bm = blockIdx.y;

    const __nv_bfloat16* Ab = g_Asp + (size_t)bm * GBM * KP;
    const __nv_bfloat16* Bb = g_Bsp + (size_t)bn * GBN * KP;

    float acc[4][4][4];
#pragma unroll
    for (int i = 0; i < 4; ++i)
#pragma unroll
        for (int j = 0; j < 4; ++j)
#pragma unroll
            for (int q = 0; q < 4; ++q) acc[i][j][q] = 0.0f;

    auto copy_stage = [&](int buf, int t) {
        const size_t kel = (size_t)t * GBK;
        const uint32_t sb = sbase + buf * STG;
#pragma unroll
        for (int i = 0; i < 4; ++i) {
            const int c = tid + 256 * i;
            const int r = (c >> 2) & 127;
            const int q = c & 3;
            if (c < 512)
                cp16(sb + r * ROWB + q * 16,
                     (const char*)(Ab + (size_t)r * KP + kel) + q * 16);
            else
                cp16(sb + GBM * ROWB + r * ROWB + q * 16,
                     (const char*)(Bb + (size_t)r * KP + kel) + q * 16);
        }
    };

    copy_stage(0, 0);
    asm volatile("cp.async.commit_group;");

    const int lrow = (lane & 7) + ((lane >> 3) & 1) * 8;
    const int lcol = (lane >> 4) << 4;

    for (int t = 0; t < NKT; ++t) {
        const int buf = t & 1;
        if (t + 1 < NKT) copy_stage(buf ^ 1, t + 1);
        asm volatile("cp.async.commit_group;");
        asm volatile("cp.async.wait_group %0;" :: "n"(1));
        __syncthreads();

        const uint32_t aBase = sbase + buf * STG + (wm * 64) * ROWB;
        const uint32_t bBase = sbase + buf * STG + GBM * ROWB + (wn * 32) * ROWB;
#pragma unroll
        for (int ks = 0; ks < 2; ++ks) {
            uint32_t af[4][4], bf[2][4];
#pragma unroll
            for (int mi = 0; mi < 4; ++mi)
                ldm_x4(af[mi], aBase + (mi * 16 + lrow) * ROWB + ks * 32 + lcol);
#pragma unroll
            for (int bj = 0; bj < 2; ++bj)
                ldm_x4(bf[bj], bBase + (bj * 16 + lrow) * ROWB + ks * 32 + lcol);
#pragma unroll
            for (int mi = 0; mi < 4; ++mi)
#pragma unroll
                for (int ni = 0; ni < 4; ++ni)
                    mma16816(acc[mi][ni], af[mi],
                             bf[ni >> 1][ni & 1], bf[ni >> 1][(ni & 1) + 2]);
        }
        __syncthreads();
    }

#pragma unroll
    for (int mi = 0; mi < 4; ++mi) {
#pragma unroll
        for (int ni = 0; ni < 4; ++ni) {
            const int m = bm * GBM + wm * 64 + mi * 16 + (lane >> 2);
            const int n = bn * GBN + wn * 32 + ni * 8 + (lane & 3) * 2;
            const float b0 = __ldg(bias + n), b1 = __ldg(bias + n + 1);
            float* p0 = g_features + (size_t)m * H_DIM + n;
            float* p1 = g_features + (size_t)(m + 8) * H_DIM + n;
            float2 v0, v1;
            v0.x = fmaxf(acc[mi][ni][0] + b0, 0.0f);
            v0.y = fmaxf(acc[mi][ni][1] + b1, 0.0f);
            v1.x = fmaxf(acc[mi][ni][2] + b0, 0.0f);
            v1.y = fmaxf(acc[mi][ni][3] + b1, 0.0f);
            *(float2*)p0 = v0;
            *(float2*)p1 = v1;
        }
    }
}

// ---------------------------------------------------------------------------
// W_dec [IN_DIM, H_DIM] -> g_WdT [H_DIM, IN_DIM]
// ---------------------------------------------------------------------------
__global__ void transpose_kernel(const float* __restrict__ in)
{
    __shared__ float tile[32][33];
    const int c0 = blockIdx.x * 32, r0 = blockIdx.y * 32;
    const int x = threadIdx.x, y = threadIdx.y;
#pragma unroll
    for (int j = 0; j < 32; j += 8)
        tile[y + j][x] = in[(size_t)(r0 + y + j) * H_DIM + c0 + x];
    __syncthreads();
#pragma unroll
    for (int j = 0; j < 32; j += 8)
        g_WdT[(size_t)(c0 + y + j) * IN_DIM + r0 + x] = tile[x][y + j];
}

// ---------------------------------------------------------------------------
// Radix select approx 64th value, then collect all candidates >= vT - DELTA.
// ---------------------------------------------------------------------------
__global__ void topk_kernel()
{
    const int row = blockIdx.x;
    const int tid = threadIdx.x;
    const float* frow = g_features + (size_t)row * H_DIM;

    __shared__ unsigned int hist[256];
    __shared__ int s_bin, s_rem;
    if (tid == 0) g_cand_cnt[row] = 0;

    unsigned int prefix = 0;
    int remaining = TOPK;
    for (int byte = 3; byte >= 0; --byte) {
        hist[tid] = 0;
        __syncthreads();
        const int shift = byte * 8;
        const unsigned int pm = (byte == 3) ? 0u : (0xFFFFFFFFu << (shift + 8));
        for (int j = tid; j < H_DIM; j += 256) {
            unsigned int u = __float_as_uint(frow[j]) | 0x80000000u;
            if ((u & pm) == prefix) atomicAdd(&hist[(u >> shift) & 0xFF], 1u);
        }
        __syncthreads();
        if (tid == 0) {
            int rem = remaining, bsel = 0;
            for (int b2 = 255; b2 >= 0; --b2) {
                int c = (int)hist[b2];
                if (rem <= c) { bsel = b2; break; }
                rem -= c;
            }
            s_bin = bsel; s_rem = rem;
        }
        __syncthreads();
        prefix |= ((unsigned int)s_bin) << shift;
        remaining = s_rem;
        __syncthreads();
    }
    const float vT = __uint_as_float(prefix ^ 0x80000000u);
    const float lim = vT - DELTA;

    for (int j = tid; j < H_DIM; j += 256) {
        if (frow[j] >= lim) {
            const int w = atomicAdd(&g_cand_cnt[row], 1);
            if (w < MAXCAND) g_cand_idx[(size_t)row * MAXCAND + w] = j;
        }
    }
}

// ---------------------------------------------------------------------------
// Exact selection: recompute Eigen-chunked fp32 dots for every candidate,
// bitonic-sort (val desc, idx asc), keep exact top-64. All output values are
// Eigen-exact -> zero selection flips, rel_err ~1e-7.
// ---------------------------------------------------------------------------
__global__ void exact_kernel(const float* __restrict__ x,
                             const float* __restrict__ W,
                             const float* __restrict__ bias)
{
    const int row = blockIdx.x;
    const int t   = threadIdx.x;
    const int cnt = min(g_cand_cnt[row], MAXCAND);

    __shared__ float sval[MAXCAND];
    __shared__ int   sidx[MAXCAND];

    float v = -1e30f;
    int   h = 0x7FFFFFFF;
    if (t < cnt) {
        h = g_cand_idx[(size_t)row * MAXCAND + t];
        const float* xr = x + (size_t)row * IN_DIM;
        const float* wr = W + (size_t)h * IN_DIM;
        float tot = 0.0f;
        int k = 0;
#pragma unroll 1
        for (int p = 0; p < 13; ++p) {
            const int len = (p < 12) ? KC : (IN_DIM - 12 * KC);
            float acc = 0.0f;
            for (int q = 0; q < len; q += 4) {
                const float4 xv = *(const float4*)(xr + k + q);
                const float4 wv = *(const float4*)(wr + k + q);
                acc = fmaf(xv.x, wv.x, acc);
                acc = fmaf(xv.y, wv.y, acc);
                acc = fmaf(xv.z, wv.z, acc);
                acc = fmaf(xv.w, wv.w, acc);
            }
            tot += acc;
            k += len;
        }
        v = tot + bias[h];
        v = v > 0.0f ? v : 0.0f;
    }
    sval[t] = v; sidx[t] = h;
    __syncthreads();

    // bitonic sort, best-first: (val desc, idx asc)
    for (int k2 = 2; k2 <= MAXCAND; k2 <<= 1) {
        for (int j = k2 >> 1; j > 0; j >>= 1) {
            const int l = t ^ j;
            if (l > t) {
                const float va = sval[t], vb = sval[l];
                const int   ia = sidx[t], ib = sidx[l];
                const bool aFirst = (va > vb) || (va == vb && ia < ib);
                const bool up = ((t & k2) == 0);
                if (up ? !aFirst : aFirst) {
                    sval[t] = vb; sval[l] = va;
                    sidx[t] = ib; sidx[l] = ia;
                }
            }
            __syncthreads();
        }
    }

    if (t < TOPK) {
        g_top_vals[(size_t)row * TOPK + t] = sval[t];
        g_top_idx [(size_t)row * TOPK + t] = sidx[t];
    }
}

// ---------------------------------------------------------------------------
// Sort picks by index (determinism) and scatter to sparse output.
// ---------------------------------------------------------------------------
__global__ void scatter_kernel(float* __restrict__ sparse)
{
    const int row = blockIdx.x;
    const int t = threadIdx.x;   // 64
    __shared__ float sv[TOPK];
    __shared__ int   si[TOPK];
    sv[t] = g_top_vals[(size_t)row * TOPK + t];
    si[t] = g_top_idx [(size_t)row * TOPK + t];
    __syncthreads();
    for (int p = 0; p < TOPK; ++p) {
        const int base = p & 1;
        if (t < TOPK / 2) {
            const int i = base + 2 * t;
            if (i + 1 < TOPK && si[i] > si[i + 1]) {
                int ti = si[i]; si[i] = si[i + 1]; si[i + 1] = ti;
                float tv = sv[i]; sv[i] = sv[i + 1]; sv[i + 1] = tv;
            }
        }
        __syncthreads();
    }
    g_top_vals[(size_t)row * TOPK + t] = sv[t];
    g_top_idx [(size_t)row * TOPK + t] = si[t];
    sparse[(size_t)row * H_DIM + si[t]] = sv[t];
}

// ---------------------------------------------------------------------------
// Sparse decode: recon[b,:] = sum_k val_k * WdT[idx_k, :]
// ---------------------------------------------------------------------------
__global__ void decode_kernel(float* __restrict__ recon)
{
    const int b = blockIdx.x;
    const int t = threadIdx.x;
    float acc[16];
#pragma unroll
    for (int i = 0; i < 16; ++i) acc[i] = 0.0f;
    for (int k = 0; k < TOPK; ++k) {
        const float val = g_top_vals[(size_t)b * TOPK + k];
        const int   idx = g_top_idx [(size_t)b * TOPK + k];
        const float4* wr = (const float4*)(g_WdT + (size_t)idx * IN_DIM);
#pragma unroll
        for (int q = 0; q < 4; ++q) {
            const float4 w = __ldg(&wr[t + q * 256]);
            acc[q * 4 + 0] = fmaf(val, w.x, acc[q * 4 + 0]);
            acc[q * 4 + 1] = fmaf(val, w.y, acc[q * 4 + 1]);
            acc[q * 4 + 2] = fmaf(val, w.z, acc[q * 4 + 2]);
            acc[q * 4 + 3] = fmaf(val, w.w, acc[q * 4 + 3]);
        }
    }
    float4* out = (float4*)(recon + (size_t)b * IN_DIM);
#pragma unroll
    for (int q = 0; q < 4; ++q)
        out[t + q * 256] = make_float4(acc[q * 4 + 0], acc[q * 4 + 1],
                                       acc[q * 4 + 2], acc[q * 4 + 3]);
}

// ---------------------------------------------------------------------------
// Launch
// ---------------------------------------------------------------------------
extern "C" void kernel_launch(void* const* d_in, const int* in_sizes, int n_in,
                              void* d_out, int out_size)
{
    const float* x     = (const float*)d_in[0];
    const float* W_enc = (const float*)d_in[1];
    const float* b_enc = (const float*)d_in[2];
    const float* W_dec = (const float*)d_in[3];

    float* out    = (float*)d_out;
    float* sparse = out;
    float* recon  = out + (size_t)BATCH * H_DIM;

    cudaMemsetAsync(sparse, 0, (size_t)BATCH * H_DIM * sizeof(float));

    split_x_kernel<<<(BATCH * IN_DIM / 4) / 256, 256>>>(x);
    split_w_kernel<<<(H_DIM * IN_DIM / 4) / 256, 256>>>(W_enc);

    dim3 gg(H_DIM / GBN, BATCH / GBM);
    gemm_kernel<<<gg, 256>>>(b_enc);

    dim3 tg(H_DIM / 32, IN_DIM / 32);
    transpose_kernel<<<tg, dim3(32, 8)>>>(W_dec);

    topk_kernel<<<BATCH, 256>>>();
    exact_kernel<<<BATCH, MAXCAND>>>(x, W_enc, b_enc);
    scatter_kernel<<<BATCH, TOPK>>>(sparse);
    decode_kernel<<<BATCH, 256>>>(recon);
}